// round 4
// baseline (speedup 1.0000x reference)
#include <cuda_runtime.h>
#include <math.h>

// Problem constants (B=4, H=16, S=1024, D=64, fp32)
#define S_LEN 1024
#define D_DIM 64
#define BH_N  64          // B*H
#define QT    16          // q rows per block
#define KTILE 256         // k columns per QK smem tile
#define VTILE 64          // k rows per PV smem tile
#define NT    256         // threads per block

#define QSTR  68          // Q tile row stride (floats), 16B-aligned, padded
#define KTSTR 257         // transposed K tile row stride: KT^T[d][k], conflict-free
#define VSTR  68          // V tile row stride

// shared memory layout (floats)
#define SS_OFF   0
#define SS_SIZE  (QT * S_LEN)            // 16384 floats: full 16x1024 score block
#define KV_OFF   (SS_OFF + SS_SIZE)
#define KV_SIZE  (D_DIM * KTSTR)         // 16448 floats: K^T tile (V tile fits inside)
#define Q_OFF    (KV_OFF + KV_SIZE)
#define Q_SIZE   (QT * QSTR)             // 1088 floats
#define SMEM_FLOATS (Q_OFF + Q_SIZE)
#define SMEM_BYTES  (SMEM_FLOATS * 4)    // 135,680 bytes

__global__ void __launch_bounds__(NT, 1)
attn_fp32_kernel(const float* __restrict__ Q, const float* __restrict__ K,
                 const float* __restrict__ V, const float* __restrict__ Bias,
                 float* __restrict__ Out, float* __restrict__ Wout)
{
    extern __shared__ float sm[];
    float* Ss = sm + SS_OFF;   // [QT][S_LEN]
    float* KV = sm + KV_OFF;   // K^T tile [D][KTSTR] or V tile [VTILE][VSTR]
    float* Qs = sm + Q_OFF;    // [QT][QSTR]

    const int t  = threadIdx.x;
    const int qt = blockIdx.x;     // 0..63
    const int bh = blockIdx.y;     // 0..63

    const float* Qg = Q + ((size_t)bh * S_LEN + (size_t)qt * QT) * D_DIM;
    const float* Kg = K + (size_t)bh * S_LEN * D_DIM;
    const float* Vg = V + (size_t)bh * S_LEN * D_DIM;

    // ---- load Q tile (16x64 floats, one float4 per thread, coalesced) ----
    {
        int r = t >> 4;               // 0..15
        int d4 = (t & 15) << 2;       // 0..60
        *(float4*)&Qs[r * QSTR + d4] = *(const float4*)&Qg[r * D_DIM + d4];
    }

    const int qg = t >> 6;   // 0..3 : q-row group (rows qg*4 .. qg*4+3), uniform per warp
    const int kc = t & 63;   // 0..63 : k column within tile (lane-consecutive)

    // =========================== Phase 1: S = Q K^T * scale ===========================
    for (int kt = 0; kt < S_LEN / KTILE; ++kt) {
        __syncthreads();
        // load K tile transposed into smem: KV[d][k], 256 rows of K, 64 d each
        #pragma unroll
        for (int i = 0; i < 16; ++i) {
            int f  = t + i * NT;            // 0..4095 float4 chunks
            int r  = f >> 4;                // 0..255 (k row in tile)
            int d4 = (f & 15) << 2;         // 0..60
            float4 kv4 = *(const float4*)&Kg[((size_t)kt * KTILE + r) * D_DIM + d4];
            KV[(d4 + 0) * KTSTR + r] = kv4.x;
            KV[(d4 + 1) * KTSTR + r] = kv4.y;
            KV[(d4 + 2) * KTSTR + r] = kv4.z;
            KV[(d4 + 3) * KTSTR + r] = kv4.w;
        }
        __syncthreads();

        float acc[4][4];
        #pragma unroll
        for (int a = 0; a < 4; ++a)
            #pragma unroll
            for (int b = 0; b < 4; ++b) acc[a][b] = 0.f;

        #pragma unroll
        for (int d = 0; d < D_DIM; ++d) {
            float rq[4], rk[4];
            #pragma unroll
            for (int iq = 0; iq < 4; ++iq)       // broadcast within warp
                rq[iq] = Qs[(qg * 4 + iq) * QSTR + d];
            #pragma unroll
            for (int ik = 0; ik < 4; ++ik)       // conflict-free: (d + kc) mod 32 distinct
                rk[ik] = KV[d * KTSTR + kc + 64 * ik];
            #pragma unroll
            for (int iq = 0; iq < 4; ++iq)
                #pragma unroll
                for (int ik = 0; ik < 4; ++ik)
                    acc[iq][ik] = fmaf(rq[iq], rk[ik], acc[iq][ik]);
        }

        #pragma unroll
        for (int iq = 0; iq < 4; ++iq)
            #pragma unroll
            for (int ik = 0; ik < 4; ++ik)
                Ss[(qg * 4 + iq) * S_LEN + kt * KTILE + kc + 64 * ik] =
                    acc[iq][ik] * 0.125f;   // 1/sqrt(64)
    }
    __syncthreads();

    // ======================= Phase 2: softmax(S + bias) per row =======================
    {
        const int w = t >> 5, lane = t & 31;
        #pragma unroll
        for (int rr = 0; rr < 2; ++rr) {
            int row   = w * 2 + rr;            // 0..15
            int qglob = qt * QT + row;
            const float* brow = Bias + (size_t)qglob * S_LEN;
            float v[32];
            float m = -INFINITY;
            #pragma unroll
            for (int j = 0; j < 32; ++j) {
                v[j] = Ss[row * S_LEN + lane + 32 * j] + brow[lane + 32 * j];
                m = fmaxf(m, v[j]);
            }
            #pragma unroll
            for (int o = 16; o; o >>= 1) m = fmaxf(m, __shfl_xor_sync(0xffffffffu, m, o));
            float sum = 0.f;
            #pragma unroll
            for (int j = 0; j < 32; ++j) { v[j] = __expf(v[j] - m); sum += v[j]; }
            #pragma unroll
            for (int o = 16; o; o >>= 1) sum += __shfl_xor_sync(0xffffffffu, sum, o);
            float inv = 1.f / sum;
            float* wrow = Wout + (size_t)bh * S_LEN * S_LEN + (size_t)qglob * S_LEN;
            #pragma unroll
            for (int j = 0; j < 32; ++j) {
                float wv = v[j] * inv;
                Ss[row * S_LEN + lane + 32 * j] = wv;   // keep for PV
                wrow[lane + 32 * j] = wv;               // attn_weights output (coalesced)
            }
        }
    }

    // =============================== Phase 3: O = W V ================================
    const int dcol = t & 63;
    float oacc[4] = {0.f, 0.f, 0.f, 0.f};
    for (int vt = 0; vt < S_LEN / VTILE; ++vt) {
        __syncthreads();   // first iter also orders Phase2 Ss writes vs Phase3 reads
        #pragma unroll
        for (int i = 0; i < 4; ++i) {
            int f  = t + i * NT;           // 0..1023 float4 chunks
            int r  = f >> 4;               // 0..63
            int d4 = (f & 15) << 2;
            *(float4*)&KV[r * VSTR + d4] =
                *(const float4*)&Vg[((size_t)vt * VTILE + r) * D_DIM + d4];
        }
        __syncthreads();
        #pragma unroll
        for (int k4 = 0; k4 < VTILE / 4; ++k4) {
            float rv[4];
            #pragma unroll
            for (int j = 0; j < 4; ++j)    // conflict-free: (4k + dcol) mod 32 distinct
                rv[j] = KV[(k4 * 4 + j) * VSTR + dcol];
            #pragma unroll
            for (int iq = 0; iq < 4; ++iq) {
                float4 rw = *(const float4*)&Ss[(qg * 4 + iq) * S_LEN + vt * VTILE + k4 * 4];
                oacc[iq] = fmaf(rw.x, rv[0], oacc[iq]);
                oacc[iq] = fmaf(rw.y, rv[1], oacc[iq]);
                oacc[iq] = fmaf(rw.z, rv[2], oacc[iq]);
                oacc[iq] = fmaf(rw.w, rv[3], oacc[iq]);
            }
        }
    }
    #pragma unroll
    for (int iq = 0; iq < 4; ++iq)
        Out[((size_t)bh * S_LEN + (size_t)qt * QT + qg * 4 + iq) * D_DIM + dcol] = oacc[iq];
}

extern "C" void kernel_launch(void* const* d_in, const int* in_sizes, int n_in,
                              void* d_out, int out_size)
{
    const float* Q    = (const float*)d_in[0];
    const float* K    = (const float*)d_in[1];
    const float* V    = (const float*)d_in[2];
    const float* Bias = (const float*)d_in[3];

    float* Out  = (float*)d_out;
    float* Wout = Out + (size_t)BH_N * S_LEN * D_DIM;   // tuple: (output, attn_weights)

    cudaFuncSetAttribute(attn_fp32_kernel,
                         cudaFuncAttributeMaxDynamicSharedMemorySize, SMEM_BYTES);

    dim3 grid(S_LEN / QT, BH_N);   // (64, 64) = 4096 blocks
    attn_fp32_kernel<<<grid, NT, SMEM_BYTES>>>(Q, K, V, Bias, Out, Wout);
}

// round 6
// speedup vs baseline: 2.7245x; 2.7245x over previous
#include <cuda_runtime.h>
#include <cuda_bf16.h>
#include <stdint.h>
#include <math.h>

#define S_LEN 1024
#define BH_N  64
#define NCH   16
#define NT    256

// dynamic smem offsets (bytes): Qhi 16K | Qlo 16K | Khi 8K | Klo 8K | Vhi 8K | Vlo 8K
#define SQH 0
#define SQL (16*1024)
#define SKH (32*1024)
#define SKL (40*1024)
#define SVH (48*1024)
#define SVL (56*1024)
#define SMEM_BYTES (64*1024)

static __device__ __forceinline__ uint32_t cvta_s(const void* p){
    uint32_t a; asm("{ .reg .u64 t; cvta.to.shared.u64 t, %1; cvt.u32.u64 %0, t; }":"=r"(a):"l"(p)); return a;
}
// swizzled addr: 128B rows of 8 16B chunks, chunk ^= row&7  (conflict-free fill + ldmatrix)
static __device__ __forceinline__ uint32_t swz(uint32_t base,int row,int col8){
    return base + (row<<7) + (((col8 ^ (row&7)))<<4);
}
static __device__ __forceinline__ void ldsm4(uint32_t a,uint32_t r[4]){
    asm volatile("ldmatrix.sync.aligned.m8n8.x4.shared.b16 {%0,%1,%2,%3},[%4];"
        :"=r"(r[0]),"=r"(r[1]),"=r"(r[2]),"=r"(r[3]):"r"(a));
}
static __device__ __forceinline__ void ldsm4t(uint32_t a,uint32_t r[4]){
    asm volatile("ldmatrix.sync.aligned.m8n8.x4.trans.shared.b16 {%0,%1,%2,%3},[%4];"
        :"=r"(r[0]),"=r"(r[1]),"=r"(r[2]),"=r"(r[3]):"r"(a));
}
static __device__ __forceinline__ void mma16816(float* d,const uint32_t* a,uint32_t b0,uint32_t b1){
    asm volatile("mma.sync.aligned.m16n8k16.row.col.f32.bf16.bf16.f32 "
        "{%0,%1,%2,%3},{%4,%5,%6,%7},{%8,%9},{%0,%1,%2,%3};"
        :"+f"(d[0]),"+f"(d[1]),"+f"(d[2]),"+f"(d[3])
        :"r"(a[0]),"r"(a[1]),"r"(a[2]),"r"(a[3]),"r"(b0),"r"(b1));
}
static __device__ __forceinline__ uint32_t pk(__nv_bfloat16 a,__nv_bfloat16 b){
    __nv_bfloat162 v(a,b); return *reinterpret_cast<uint32_t*>(&v);
}
static __device__ __forceinline__ void sts16(uint32_t a,const uint32_t r[4]){
    asm volatile("st.shared.v4.b32 [%0],{%1,%2,%3,%4};"
        ::"r"(a),"r"(r[0]),"r"(r[1]),"r"(r[2]),"r"(r[3]):"memory");
}

// fill ROWS x 64 fp32 row-major gmem tile -> bf16 hi/lo split, swizzled smem
template<int ROWS>
static __device__ __forceinline__ void fill(const float* __restrict__ g, uint32_t shi, uint32_t slo, int t){
    #pragma unroll
    for(int i=0;i<ROWS/32;++i){
        int c16=t+i*256;                  // 16B-chunk id
        int row=c16>>3, col8=c16&7;
        float4 a=__ldg((const float4*)(g+row*64+col8*8));
        float4 b=__ldg((const float4*)(g+row*64+col8*8)+1);
        float f[8]={a.x,a.y,a.z,a.w,b.x,b.y,b.z,b.w};
        uint32_t h[4],l[4];
        #pragma unroll
        for(int k=0;k<4;++k){
            float x=f[2*k], y=f[2*k+1];
            __nv_bfloat16 hx=__float2bfloat16(x), hy=__float2bfloat16(y);
            __nv_bfloat16 lx=__float2bfloat16(x-__bfloat162float(hx));
            __nv_bfloat16 ly=__float2bfloat16(y-__bfloat162float(hy));
            h[k]=pk(hx,hy); l[k]=pk(lx,ly);
        }
        uint32_t off=(uint32_t)((row<<7)+(((col8^(row&7)))<<4));
        sts16(shi+off,h); sts16(slo+off,l);
    }
}

__global__ void __launch_bounds__(NT,2) attn_mma_kernel(
    const float* __restrict__ Q,const float* __restrict__ K,const float* __restrict__ V,
    const float* __restrict__ Bias,float* __restrict__ Out,float* __restrict__ Wout)
{
    extern __shared__ char smem[];
    const uint32_t sb=cvta_s(smem);
    const int t=threadIdx.x, w=t>>5, lane=t&31;
    const int qt=blockIdx.x, bh=blockIdx.y;
    const int qr=lane>>2, qc=(lane&3)*2;
    const int m0=qt*128;
    const int row_lo=m0+w*16+qr, row_hi=row_lo+8;

    const float* Kg=K+(size_t)bh*S_LEN*64;
    const float* Vg=V+(size_t)bh*S_LEN*64;

    // Q tile (128x64) -> smem bf16 split, once
    fill<128>(Q+((size_t)bh*S_LEN+m0)*64, sb+SQH, sb+SQL, t);

    // ldmatrix per-thread address components
    const int arow=16*w+(lane&7)+8*((lane>>3)&1);   // A (Q/P layout): rows of warp tile
    const int acolb=lane>>4;                        // 0/1 -> k-halves
    const int brow7=lane&7, bcol=lane>>3;           // B (K): n rows, k chunk

    const float* bias_lo=Bias+(size_t)row_lo*S_LEN;
    const float* bias_hi=Bias+(size_t)row_hi*S_LEN;

    float sum_lo=0.f,sum_hi=0.f;
    __syncthreads();

    // ============================ PASS 1: row sums ============================
    for(int c=0;c<NCH;++c){
        if(c) __syncthreads();
        fill<64>(Kg+(size_t)c*4096, sb+SKH, sb+SKL, t);
        __syncthreads();
        uint32_t Ah[4][4],Al[4][4];
        #pragma unroll
        for(int ks=0;ks<4;++ks){
            ldsm4(swz(sb+SQH,arow,2*ks+acolb),Ah[ks]);
            ldsm4(swz(sb+SQL,arow,2*ks+acolb),Al[ks]);
        }
        #pragma unroll
        for(int j=0;j<8;++j){
            float Sj[4]={0.f,0.f,0.f,0.f};
            #pragma unroll
            for(int s2=0;s2<2;++s2){
                uint32_t Bh[4],Bl[4];
                ldsm4(swz(sb+SKH,8*j+brow7,4*s2+bcol),Bh);
                ldsm4(swz(sb+SKL,8*j+brow7,4*s2+bcol),Bl);
                #pragma unroll
                for(int s=0;s<2;++s){
                    mma16816(Sj,Ah[2*s2+s],Bh[2*s],Bh[2*s+1]);
                    mma16816(Sj,Ah[2*s2+s],Bl[2*s],Bl[2*s+1]);
                    mma16816(Sj,Al[2*s2+s],Bh[2*s],Bh[2*s+1]);
                }
            }
            float2 blo=__ldg((const float2*)(bias_lo+c*64+8*j+qc));
            float2 bhi=__ldg((const float2*)(bias_hi+c*64+8*j+qc));
            sum_lo+=__expf(fmaf(Sj[0],0.125f,blo.x))+__expf(fmaf(Sj[1],0.125f,blo.y));
            sum_hi+=__expf(fmaf(Sj[2],0.125f,bhi.x))+__expf(fmaf(Sj[3],0.125f,bhi.y));
        }
    }
    sum_lo+=__shfl_xor_sync(~0u,sum_lo,1); sum_lo+=__shfl_xor_sync(~0u,sum_lo,2);
    sum_hi+=__shfl_xor_sync(~0u,sum_hi,1); sum_hi+=__shfl_xor_sync(~0u,sum_hi,2);
    const float inv_lo=1.f/sum_lo, inv_hi=1.f/sum_hi;

    float O[8][4];
    #pragma unroll
    for(int j=0;j<8;++j){O[j][0]=0.f;O[j][1]=0.f;O[j][2]=0.f;O[j][3]=0.f;}

    float* w_lo=Wout+((size_t)bh<<20)+(size_t)row_lo*S_LEN;
    float* w_hi=Wout+((size_t)bh<<20)+(size_t)row_hi*S_LEN;

    // =================== PASS 2: weights out + PV accumulate ===================
    for(int c=0;c<NCH;++c){
        __syncthreads();
        fill<64>(Kg+(size_t)c*4096, sb+SKH, sb+SKL, t);
        fill<64>(Vg+(size_t)c*4096, sb+SVH, sb+SVL, t);
        __syncthreads();
        uint32_t Ah[4][4],Al[4][4];
        #pragma unroll
        for(int ks=0;ks<4;++ks){
            ldsm4(swz(sb+SQH,arow,2*ks+acolb),Ah[ks]);
            ldsm4(swz(sb+SQL,arow,2*ks+acolb),Al[ks]);
        }
        uint32_t Ph[4][4],Pl[4][4];
        #pragma unroll
        for(int j=0;j<8;++j){
            float Sj[4]={0.f,0.f,0.f,0.f};
            #pragma unroll
            for(int s2=0;s2<2;++s2){
                uint32_t Bh[4],Bl[4];
                ldsm4(swz(sb+SKH,8*j+brow7,4*s2+bcol),Bh);
                ldsm4(swz(sb+SKL,8*j+brow7,4*s2+bcol),Bl);
                #pragma unroll
                for(int s=0;s<2;++s){
                    mma16816(Sj,Ah[2*s2+s],Bh[2*s],Bh[2*s+1]);
                    mma16816(Sj,Ah[2*s2+s],Bl[2*s],Bl[2*s+1]);
                    mma16816(Sj,Al[2*s2+s],Bh[2*s],Bh[2*s+1]);
                }
            }
            float2 blo=__ldg((const float2*)(bias_lo+c*64+8*j+qc));
            float2 bhi=__ldg((const float2*)(bias_hi+c*64+8*j+qc));
            float p0=__expf(fmaf(Sj[0],0.125f,blo.x))*inv_lo;
            float p1=__expf(fmaf(Sj[1],0.125f,blo.y))*inv_lo;
            float p2=__expf(fmaf(Sj[2],0.125f,bhi.x))*inv_hi;
            float p3=__expf(fmaf(Sj[3],0.125f,bhi.y))*inv_hi;
            asm volatile("st.global.cs.v2.f32 [%0],{%1,%2};"::"l"(w_lo+c*64+8*j+qc),"f"(p0),"f"(p1):"memory");
            asm volatile("st.global.cs.v2.f32 [%0],{%1,%2};"::"l"(w_hi+c*64+8*j+qc),"f"(p2),"f"(p3):"memory");
            // S-fragment -> P A-fragment (layouts coincide): ntile j feeds kstep j/2
            __nv_bfloat16 h0=__float2bfloat16(p0),h1=__float2bfloat16(p1);
            __nv_bfloat16 h2=__float2bfloat16(p2),h3=__float2bfloat16(p3);
            int s=j>>1, b2=2*(j&1);
            Ph[s][b2]  =pk(h0,h1);
            Ph[s][b2+1]=pk(h2,h3);
            Pl[s][b2]  =pk(__float2bfloat16(p0-__bfloat162float(h0)),
                           __float2bfloat16(p1-__bfloat162float(h1)));
            Pl[s][b2+1]=pk(__float2bfloat16(p2-__bfloat162float(h2)),
                           __float2bfloat16(p3-__bfloat162float(h3)));
        }
        // PV: O[m][d] += P[m][k] * V[k][d]   (B via ldmatrix.trans from row-major V)
        #pragma unroll
        for(int j=0;j<8;++j){
            #pragma unroll
            for(int s2=0;s2<2;++s2){
                uint32_t Bh[4],Bl[4];
                int vr=32*s2+lane;
                ldsm4t(swz(sb+SVH,vr,j),Bh);
                ldsm4t(swz(sb+SVL,vr,j),Bl);
                #pragma unroll
                for(int s=0;s<2;++s){
                    mma16816(O[j],Ph[2*s2+s],Bh[2*s],Bh[2*s+1]);
                    mma16816(O[j],Ph[2*s2+s],Bl[2*s],Bl[2*s+1]);
                    mma16816(O[j],Pl[2*s2+s],Bh[2*s],Bh[2*s+1]);
                }
            }
        }
    }
    // -------- epilogue: O fragments -> gmem --------
    float* o_lo=Out+((size_t)bh*S_LEN+row_lo)*64;
    float* o_hi=Out+((size_t)bh*S_LEN+row_hi)*64;
    #pragma unroll
    for(int j=0;j<8;++j){
        *(float2*)(o_lo+8*j+qc)=make_float2(O[j][0],O[j][1]);
        *(float2*)(o_hi+8*j+qc)=make_float2(O[j][2],O[j][3]);
    }
}

extern "C" void kernel_launch(void* const* d_in, const int* in_sizes, int n_in,
                              void* d_out, int out_size)
{
    const float* Q=(const float*)d_in[0];
    const float* K=(const float*)d_in[1];
    const float* V=(const float*)d_in[2];
    const float* Bias=(const float*)d_in[3];
    float* Out=(float*)d_out;
    float* Wout=Out+(size_t)BH_N*S_LEN*64;   // tuple: (output, attn_weights)

    cudaFuncSetAttribute(attn_mma_kernel,
                         cudaFuncAttributeMaxDynamicSharedMemorySize, SMEM_BYTES);
    dim3 grid(S_LEN/128, BH_N);   // (8, 64)
    attn_mma_kernel<<<grid,NT,SMEM_BYTES>>>(Q,K,V,Bias,Out,Wout);
}